// round 4
// baseline (speedup 1.0000x reference)
#include <cuda_runtime.h>
#include <math.h>
#include <stdint.h>

// Problem shapes (fixed by setup_inputs)
#define D_DIM  1024
#define C_CLS  1000
#define B_ROWS 4096
#define M_ROWS 32768
#define TEMP_INV 10.0f
#define EPSF 1e-8f
#define HARD_K 10

typedef unsigned long long ull;

// ---------------- device scratch (static: no allocations allowed) ----------------
__device__ float g_zimg[(size_t)B_ROWS * D_DIM];          // 16 MB
__device__ float g_zp[(size_t)C_CLS * D_DIM];             // 4 MB
__device__ float g_sim[(size_t)M_ROWS * C_CLS];           // 131 MB (max unique rows = M)
__device__ float g_w[C_CLS];
__device__ int   g_counts[C_CLS];
__device__ double g_loss;
__device__ double g_nvalid;

#define NEG_INF (__int_as_float(0xff800000))

// ---------------- block reductions (blockDim.x multiple of 32, <= 1024) ----------------
__device__ __forceinline__ float blockReduceSumF(float v, float* sred) {
    int lane = threadIdx.x & 31, wid = threadIdx.x >> 5;
    int nw = blockDim.x >> 5;
    #pragma unroll
    for (int o = 16; o; o >>= 1) v += __shfl_xor_sync(0xffffffffu, v, o);
    if (lane == 0) sred[wid] = v;
    __syncthreads();
    if (wid == 0) {
        v = (lane < nw) ? sred[lane] : 0.0f;
        #pragma unroll
        for (int o = 16; o; o >>= 1) v += __shfl_xor_sync(0xffffffffu, v, o);
        if (lane == 0) sred[0] = v;
    }
    __syncthreads();
    v = sred[0];
    __syncthreads();
    return v;
}

__device__ __forceinline__ float blockReduceMaxF(float v, float* sred) {
    int lane = threadIdx.x & 31, wid = threadIdx.x >> 5;
    int nw = blockDim.x >> 5;
    #pragma unroll
    for (int o = 16; o; o >>= 1) v = fmaxf(v, __shfl_xor_sync(0xffffffffu, v, o));
    if (lane == 0) sred[wid] = v;
    __syncthreads();
    if (wid == 0) {
        v = (lane < nw) ? sred[lane] : NEG_INF;
        #pragma unroll
        for (int o = 16; o; o >>= 1) v = fmaxf(v, __shfl_xor_sync(0xffffffffu, v, o));
        if (lane == 0) sred[0] = v;
    }
    __syncthreads();
    v = sred[0];
    __syncthreads();
    return v;
}

__device__ __forceinline__ int blockReduceMinI(int v, int* sred) {
    int lane = threadIdx.x & 31, wid = threadIdx.x >> 5;
    int nw = blockDim.x >> 5;
    #pragma unroll
    for (int o = 16; o; o >>= 1) v = min(v, __shfl_xor_sync(0xffffffffu, v, o));
    if (lane == 0) sred[wid] = v;
    __syncthreads();
    if (wid == 0) {
        v = (lane < nw) ? sred[lane] : 0x7fffffff;
        #pragma unroll
        for (int o = 16; o; o >>= 1) v = min(v, __shfl_xor_sync(0xffffffffu, v, o));
        if (lane == 0) sred[0] = v;
    }
    __syncthreads();
    v = sred[0];
    __syncthreads();
    return v;
}

// ---------------- init: zero per-replay accumulators ----------------
__global__ void init_kernel() {
    int t = threadIdx.x;
    if (t < C_CLS) g_counts[t] = 0;
    if (t == 0) { g_loss = 0.0; g_nvalid = 0.0; }
}

// ---------------- row l2 normalize ----------------
__global__ void norm_rows_kernel(const float* __restrict__ in, float* __restrict__ out) {
    int r = blockIdx.x;
    const float* x = in + (size_t)r * D_DIM;
    float* y = out + (size_t)r * D_DIM;
    __shared__ float sred[32];
    float ss = 0.0f;
    for (int c = threadIdx.x; c < D_DIM; c += blockDim.x) {
        float v = x[c];
        ss += v * v;
    }
    ss = blockReduceSumF(ss, sred);
    float inv = rsqrtf(ss + 1e-24f);
    for (int c = threadIdx.x; c < D_DIM; c += blockDim.x) y[c] = x[c] * inv;
}

// ---------------- class counts ----------------
__global__ void counts_kernel(const int* __restrict__ labels) {
    int c = blockIdx.x * blockDim.x + threadIdx.x;
    if (c >= C_CLS) return;
    int r0 = blockIdx.y * 64;
    int s = 0;
    #pragma unroll 4
    for (int i = 0; i < 64; i++) s += labels[(size_t)(r0 + i) * C_CLS + c];
    atomicAdd(&g_counts[c], s);
}

// ---------------- class-balanced weights ----------------
__global__ void weights_kernel() {
    __shared__ float sred[32];
    int c = threadIdx.x;
    float w = 0.0f;
    if (c < C_CLS) {
        float cnt = (float)g_counts[c];
        float eff = 1.0f - powf(0.999f, cnt);
        w = (1.0f - 0.999f) / (eff + EPSF);
    }
    float tot = blockReduceSumF(w, sred);
    if (c < C_CLS) g_w[c] = w / tot * (float)C_CLS;
}

// ---------------- fused-gather SGEMM: sim = E @ zpT * 10 ----------------
// BM=128, BN=128, BK=16, 256 threads, 8x8 microtile with fma.rn.f32x2
#define BM 128
#define BN 128
#define BK 16

union F4U { float4 v; ull u[2]; };
union F2U { ull u; float2 f; };

#define PACK2(dst, a)   asm("mov.b64 %0, {%1, %1};" : "=l"(dst) : "f"(a))
#define FMA2(acc, a, b) asm("fma.rn.f32x2 %0, %1, %2, %0;" : "+l"(acc) : "l"(a), "l"(b))

__device__ __forceinline__ const float* rowPtrA(int r, const float* __restrict__ memF) {
    return (r < B_ROWS) ? (g_zimg + (size_t)r * D_DIM)
                        : (memF + (size_t)(r - B_ROWS) * D_DIM);
}

__global__ void __launch_bounds__(256, 2) gemm_kernel(const float* __restrict__ memF,
                                                      const int* __restrict__ memptr_p) {
    int rowsEff = B_ROWS + memptr_p[0];
    int rowBase = blockIdx.y * BM;
    if (rowBase >= rowsEff) return;
    int colBase = blockIdx.x * BN;

    __shared__ float As[BK][BM + 4];
    __shared__ float Bs[BK][BN + 4];

    int tid = threadIdx.x;
    int tx = tid & 15, ty = tid >> 4;
    int m0 = ty * 8, n0 = tx * 8;

    // load-index precompute: 512 float4 per tile, 2 per thread
    int v0 = tid, v1 = tid + 256;
    int arow0 = v0 >> 2, ak0 = (v0 & 3) * 4;
    int arow1 = v1 >> 2, ak1 = (v1 & 3) * 4;
    const float* aPtr0 = rowPtrA(rowBase + arow0, memF);
    const float* aPtr1 = rowPtrA(rowBase + arow1, memF);
    int bcol0 = colBase + arow0, bcol1 = colBase + arow1;
    const float* bPtr0 = g_zp + (size_t)min(bcol0, C_CLS - 1) * D_DIM;
    const float* bPtr1 = g_zp + (size_t)min(bcol1, C_CLS - 1) * D_DIM;
    bool bok0 = (bcol0 < C_CLS), bok1 = (bcol1 < C_CLS);

    ull acc[8][4];
    #pragma unroll
    for (int m = 0; m < 8; m++)
        #pragma unroll
        for (int p = 0; p < 4; p++) acc[m][p] = 0ull;

    const int NT = D_DIM / BK;
    float4 aR0, aR1, bR0, bR1;
    // prologue loads (kt = 0)
    aR0 = *(const float4*)(aPtr0 + ak0);
    aR1 = *(const float4*)(aPtr1 + ak1);
    bR0 = bok0 ? *(const float4*)(bPtr0 + ak0) : make_float4(0, 0, 0, 0);
    bR1 = bok1 ? *(const float4*)(bPtr1 + ak1) : make_float4(0, 0, 0, 0);

    for (int kt = 0; kt < NT; kt++) {
        __syncthreads();
        // scatter (transpose) to smem
        As[(ak0 >> 2) * 4 + 0][arow0] = aR0.x; As[(ak0 >> 2) * 4 + 1][arow0] = aR0.y;
        As[(ak0 >> 2) * 4 + 2][arow0] = aR0.z; As[(ak0 >> 2) * 4 + 3][arow0] = aR0.w;
        As[(ak1 >> 2) * 4 + 0][arow1] = aR1.x; As[(ak1 >> 2) * 4 + 1][arow1] = aR1.y;
        As[(ak1 >> 2) * 4 + 2][arow1] = aR1.z; As[(ak1 >> 2) * 4 + 3][arow1] = aR1.w;
        Bs[(ak0 >> 2) * 4 + 0][arow0] = bR0.x; Bs[(ak0 >> 2) * 4 + 1][arow0] = bR0.y;
        Bs[(ak0 >> 2) * 4 + 2][arow0] = bR0.z; Bs[(ak0 >> 2) * 4 + 3][arow0] = bR0.w;
        Bs[(ak1 >> 2) * 4 + 0][arow1] = bR1.x; Bs[(ak1 >> 2) * 4 + 1][arow1] = bR1.y;
        Bs[(ak1 >> 2) * 4 + 2][arow1] = bR1.z; Bs[(ak1 >> 2) * 4 + 3][arow1] = bR1.w;
        __syncthreads();

        if (kt + 1 < NT) {   // prefetch next tile into regs while computing
            int koff = (kt + 1) * BK;
            aR0 = *(const float4*)(aPtr0 + koff + ak0);
            aR1 = *(const float4*)(aPtr1 + koff + ak1);
            bR0 = bok0 ? *(const float4*)(bPtr0 + koff + ak0) : make_float4(0, 0, 0, 0);
            bR1 = bok1 ? *(const float4*)(bPtr1 + koff + ak1) : make_float4(0, 0, 0, 0);
        }

        #pragma unroll
        for (int k = 0; k < BK; k++) {
            float4 a0 = *(const float4*)(&As[k][m0]);
            float4 a1 = *(const float4*)(&As[k][m0 + 4]);
            F4U b0u, b1u;
            b0u.v = *(const float4*)(&Bs[k][n0]);
            b1u.v = *(const float4*)(&Bs[k][n0 + 4]);
            float av[8] = {a0.x, a0.y, a0.z, a0.w, a1.x, a1.y, a1.z, a1.w};
            #pragma unroll
            for (int m = 0; m < 8; m++) {
                ull ap; PACK2(ap, av[m]);
                FMA2(acc[m][0], ap, b0u.u[0]);
                FMA2(acc[m][1], ap, b0u.u[1]);
                FMA2(acc[m][2], ap, b1u.u[0]);
                FMA2(acc[m][3], ap, b1u.u[1]);
            }
        }
    }

    // store sim = acc * 10
    bool fullCols = (colBase + BN <= C_CLS);
    #pragma unroll
    for (int m = 0; m < 8; m++) {
        int r = rowBase + m0 + m;
        F2U p0, p1, p2, p3;
        p0.u = acc[m][0]; p1.u = acc[m][1]; p2.u = acc[m][2]; p3.u = acc[m][3];
        float vals[8] = {p0.f.x, p0.f.y, p1.f.x, p1.f.y, p2.f.x, p2.f.y, p3.f.x, p3.f.y};
        size_t base = (size_t)r * C_CLS + colBase + n0;
        if (fullCols) {
            float4 o0 = make_float4(vals[0] * TEMP_INV, vals[1] * TEMP_INV, vals[2] * TEMP_INV, vals[3] * TEMP_INV);
            float4 o1 = make_float4(vals[4] * TEMP_INV, vals[5] * TEMP_INV, vals[6] * TEMP_INV, vals[7] * TEMP_INV);
            *(float4*)(&g_sim[base]) = o0;
            *(float4*)(&g_sim[base + 4]) = o1;
        } else {
            #pragma unroll
            for (int j = 0; j < 8; j++) {
                int c = colBase + n0 + j;
                if (c < C_CLS) g_sim[(size_t)r * C_CLS + c] = vals[j] * TEMP_INV;
            }
        }
    }
}

// ---------------- per-row epilogue: exact top-10 threshold + masked LSE + loss ----------------
__global__ void epilogue_kernel(const int* __restrict__ labels,
                                const int* __restrict__ memL,
                                const int* __restrict__ memptr_p) {
    int r = blockIdx.x;
    int mp = memptr_p[0];
    int rowsEff = B_ROWS + mp;
    if (r >= rowsEff) return;

    const int* lab = (r < B_ROWS) ? (labels + (size_t)r * C_CLS)
                                  : (memL + (size_t)(r - B_ROWS) * C_CLS);
    float wfac = (r < B_ROWS) ? 2.0f : 1.0f;   // z_img rows appear twice in enhanced set

    __shared__ float s_sim[C_CLS];
    __shared__ float s_neg[C_CLS];
    __shared__ unsigned char s_pos[C_CLS];
    __shared__ float sredf[32];
    __shared__ int sredi[32];

    const float* simRow = g_sim + (size_t)r * C_CLS;
    for (int c = threadIdx.x; c < C_CLS; c += blockDim.x) {
        float sv = simRow[c];
        int pos = (lab[c] > 0);
        s_sim[c] = sv;
        s_pos[c] = (unsigned char)pos;
        s_neg[c] = pos ? NEG_INF : sv;
    }
    __syncthreads();

    // exact 10th order statistic of negatives (remove exactly one instance per pass)
    float thr = NEG_INF;
    for (int it = 0; it < HARD_K; it++) {
        float lm = NEG_INF;
        for (int c = threadIdx.x; c < C_CLS; c += blockDim.x) lm = fmaxf(lm, s_neg[c]);
        lm = blockReduceMaxF(lm, sredf);
        thr = lm;
        if (lm == NEG_INF) break;   // fewer than K negatives -> threshold -inf
        if (it < HARD_K - 1) {
            int mi = 0x7fffffff;
            for (int c = threadIdx.x; c < C_CLS; c += blockDim.x)
                if (s_neg[c] == lm) mi = min(mi, c);
            mi = blockReduceMinI(mi, sredi);
            if (threadIdx.x == 0) s_neg[mi] = NEG_INF;
            __syncthreads();
        }
    }

    // masked LSE: mask = pos | (sim >= thr)
    float lm2 = NEG_INF;
    for (int c = threadIdx.x; c < C_CLS; c += blockDim.x) {
        if (s_pos[c] || s_sim[c] >= thr) lm2 = fmaxf(lm2, s_sim[c]);
    }
    float mx = blockReduceMaxF(lm2, sredf);

    float se = 0.0f;
    for (int c = threadIdx.x; c < C_CLS; c += blockDim.x) {
        if (s_pos[c] || s_sim[c] >= thr) se += expf(s_sim[c] - mx);
    }
    se = blockReduceSumF(se, sredf);
    float lse = mx + logf(se);

    float ws = 0.0f, ln = 0.0f;
    for (int c = threadIdx.x; c < C_CLS; c += blockDim.x) {
        if (s_pos[c]) {
            float w = g_w[c];
            ws += w;
            ln += w * (lse - s_sim[c]);
        }
    }
    ws = blockReduceSumF(ws, sredf);
    ln = blockReduceSumF(ln, sredf);

    if (threadIdx.x == 0 && ws > 0.0f) {
        atomicAdd(&g_loss, (double)(wfac * (ln / (ws + EPSF))));
        atomicAdd(&g_nvalid, (double)wfac);
    }
}

__global__ void finalize_kernel(float* __restrict__ out) {
    double nv = g_nvalid;
    if (nv < 1.0) nv = 1.0;
    out[0] = (float)(g_loss / nv);
}

// ---------------- launch ----------------
extern "C" void kernel_launch(void* const* d_in, const int* in_sizes, int n_in,
                              void* d_out, int out_size) {
    const float* img     = (const float*)d_in[0];
    const float* prompts = (const float*)d_in[1];
    const int*   labels  = (const int*)d_in[2];
    const float* memF    = (const float*)d_in[3];
    const int*   memL    = (const int*)d_in[4];
    const int*   memptr  = (const int*)d_in[5];
    float* out = (float*)d_out;
    (void)in_sizes; (void)n_in; (void)out_size;

    float* zp_ptr; cudaGetSymbolAddress((void**)&zp_ptr, g_zp);
    float* zi_ptr; cudaGetSymbolAddress((void**)&zi_ptr, g_zimg);

    init_kernel<<<1, 1024>>>();
    norm_rows_kernel<<<C_CLS, 256>>>(prompts, zp_ptr);
    norm_rows_kernel<<<B_ROWS, 256>>>(img, zi_ptr);
    counts_kernel<<<dim3((C_CLS + 255) / 256, B_ROWS / 64), 256>>>(labels);
    weights_kernel<<<1, 1024>>>();
    gemm_kernel<<<dim3((C_CLS + BN - 1) / BN, M_ROWS / BM), 256>>>(memF, memptr);
    epilogue_kernel<<<M_ROWS, 256>>>(labels, memL, memptr);
    finalize_kernel<<<1, 1>>>(out);
}

// round 6
// speedup vs baseline: 3.1479x; 3.1479x over previous
#include <cuda_runtime.h>
#include <cuda_bf16.h>
#include <math.h>
#include <stdint.h>

#define D_DIM  1024
#define C_CLS  1000
#define B_ROWS 4096
#define M_ROWS 32768
#define MAXR   (B_ROWS + M_ROWS)   // 36864 max enhanced unique rows
#define TEMP_INV 10.0f
#define EPSF 1e-8f
#define HARD_K 10

typedef unsigned long long ull;

// ---------------- device scratch ----------------
__device__ __nv_bfloat16 g_A16[(size_t)MAXR * D_DIM];   // 75.5 MB (rows: z_img | memF)
__device__ __nv_bfloat16 g_B16[(size_t)1024 * D_DIM];   // 2 MB (z_prompts, padded to 1024 rows)
__device__ float g_sim[(size_t)MAXR * C_CLS];           // 147 MB
__device__ float g_w[C_CLS];
__device__ int   g_counts[C_CLS];
__device__ double g_loss;
__device__ double g_nvalid;

#define NEG_INF (__int_as_float(0xff800000))

// ---------------- PTX helpers (non-arch-specific: sm_80+ ISA only) ----------------
__device__ __forceinline__ uint32_t smem_to_u32(const void* p) {
    uint32_t a;
    asm("{ .reg .u64 t; cvta.to.shared.u64 t, %1; cvt.u32.u64 %0, t; }" : "=r"(a) : "l"(p));
    return a;
}
__device__ __forceinline__ void cp16(uint32_t s, const void* g) {
    asm volatile("cp.async.cg.shared.global [%0], [%1], 16;" :: "r"(s), "l"(g) : "memory");
}
#define CP_COMMIT() asm volatile("cp.async.commit_group;" ::: "memory")
#define CP_WAIT1()  asm volatile("cp.async.wait_group 1;" ::: "memory")

#define LDSM4(r, addr) \
    asm volatile("ldmatrix.sync.aligned.m8n8.x4.shared.b16 {%0,%1,%2,%3}, [%4];" \
        : "=r"((r)[0]), "=r"((r)[1]), "=r"((r)[2]), "=r"((r)[3]) : "r"(addr))

#define MMA16816(c, a, b0, b1) \
    asm volatile("mma.sync.aligned.m16n8k16.row.col.f32.bf16.bf16.f32 " \
        "{%0,%1,%2,%3}, {%4,%5,%6,%7}, {%8,%9}, {%0,%1,%2,%3};" \
        : "+f"((c)[0]), "+f"((c)[1]), "+f"((c)[2]), "+f"((c)[3]) \
        : "r"((a)[0]), "r"((a)[1]), "r"((a)[2]), "r"((a)[3]), "r"(b0), "r"(b1))

// ---------------- block reductions ----------------
__device__ __forceinline__ float blockReduceSumF(float v, float* sred) {
    int lane = threadIdx.x & 31, wid = threadIdx.x >> 5;
    int nw = blockDim.x >> 5;
    #pragma unroll
    for (int o = 16; o; o >>= 1) v += __shfl_xor_sync(0xffffffffu, v, o);
    if (lane == 0) sred[wid] = v;
    __syncthreads();
    if (wid == 0) {
        v = (lane < nw) ? sred[lane] : 0.0f;
        #pragma unroll
        for (int o = 16; o; o >>= 1) v += __shfl_xor_sync(0xffffffffu, v, o);
        if (lane == 0) sred[0] = v;
    }
    __syncthreads();
    v = sred[0];
    __syncthreads();
    return v;
}
__device__ __forceinline__ float blockReduceMaxF(float v, float* sred) {
    int lane = threadIdx.x & 31, wid = threadIdx.x >> 5;
    int nw = blockDim.x >> 5;
    #pragma unroll
    for (int o = 16; o; o >>= 1) v = fmaxf(v, __shfl_xor_sync(0xffffffffu, v, o));
    if (lane == 0) sred[wid] = v;
    __syncthreads();
    if (wid == 0) {
        v = (lane < nw) ? sred[lane] : NEG_INF;
        #pragma unroll
        for (int o = 16; o; o >>= 1) v = fmaxf(v, __shfl_xor_sync(0xffffffffu, v, o));
        if (lane == 0) sred[0] = v;
    }
    __syncthreads();
    v = sred[0];
    __syncthreads();
    return v;
}

// ---------------- small kernels ----------------
__global__ void init_kernel() {
    int t = threadIdx.x;
    if (t < C_CLS) g_counts[t] = 0;
    if (t == 0) { g_loss = 0.0; g_nvalid = 0.0; }
}

// normalize prompts -> g_B16 (rows >= C zero-padded). grid 1024, 256 thr
__global__ void norm_prompts_kernel(const float* __restrict__ prompts) {
    int r = blockIdx.x;
    uint2* dst = (uint2*)(g_B16 + (size_t)r * D_DIM);
    int t = threadIdx.x;
    if (r >= C_CLS) { dst[t] = make_uint2(0u, 0u); return; }
    __shared__ float sred[32];
    const float4* src = (const float4*)(prompts + (size_t)r * D_DIM);
    float4 v = src[t];
    float ss = v.x * v.x + v.y * v.y + v.z * v.z + v.w * v.w;
    ss = blockReduceSumF(ss, sred);
    float inv = rsqrtf(ss + 1e-24f);
    __nv_bfloat162 lo = __floats2bfloat162_rn(v.x * inv, v.y * inv);
    __nv_bfloat162 hi = __floats2bfloat162_rn(v.z * inv, v.w * inv);
    dst[t] = make_uint2(*(uint32_t*)&lo, *(uint32_t*)&hi);
}

// normalize images -> g_A16 rows [0, B). grid 4096, 256 thr
__global__ void norm_img_kernel(const float* __restrict__ img) {
    int r = blockIdx.x;
    int t = threadIdx.x;
    __shared__ float sred[32];
    const float4* src = (const float4*)(img + (size_t)r * D_DIM);
    float4 v = src[t];
    float ss = v.x * v.x + v.y * v.y + v.z * v.z + v.w * v.w;
    ss = blockReduceSumF(ss, sred);
    float inv = rsqrtf(ss + 1e-24f);
    __nv_bfloat162 lo = __floats2bfloat162_rn(v.x * inv, v.y * inv);
    __nv_bfloat162 hi = __floats2bfloat162_rn(v.z * inv, v.w * inv);
    uint2* dst = (uint2*)(g_A16 + (size_t)r * D_DIM);
    dst[t] = make_uint2(*(uint32_t*)&lo, *(uint32_t*)&hi);
}

// memF rows [0, mem_ptr) -> g_A16 rows [B, B+mem_ptr). grid 32768, 256 thr
__global__ void conv_mem_kernel(const float* __restrict__ memF, const int* __restrict__ memptr_p) {
    int r = blockIdx.x;
    if (r >= memptr_p[0]) return;
    int t = threadIdx.x;
    const float4* src = (const float4*)(memF + (size_t)r * D_DIM);
    float4 v = src[t];
    __nv_bfloat162 lo = __floats2bfloat162_rn(v.x, v.y);
    __nv_bfloat162 hi = __floats2bfloat162_rn(v.z, v.w);
    uint2* dst = (uint2*)(g_A16 + (size_t)(B_ROWS + r) * D_DIM);
    dst[t] = make_uint2(*(uint32_t*)&lo, *(uint32_t*)&hi);
}

// class counts: grid (4, 32), 256 thr
__global__ void counts_kernel(const int* __restrict__ labels) {
    int c = blockIdx.x * blockDim.x + threadIdx.x;
    if (c >= C_CLS) return;
    const int* p = labels + (size_t)(blockIdx.y * 128) * C_CLS + c;
    int s = 0;
    #pragma unroll 8
    for (int i = 0; i < 128; i++) s += p[(size_t)i * C_CLS];
    atomicAdd(&g_counts[c], s);
}

__global__ void weights_kernel() {
    __shared__ float sred[32];
    int c = threadIdx.x;
    float w = 0.0f;
    if (c < C_CLS) {
        float cnt = (float)g_counts[c];
        float eff = 1.0f - powf(0.999f, cnt);
        w = (1.0f - 0.999f) / (eff + EPSF);
    }
    float tot = blockReduceSumF(w, sred);
    if (c < C_CLS) g_w[c] = w / tot * (float)C_CLS;
}

// ---------------- bf16 mma.sync GEMM: sim = A16 @ B16^T * 10 ----------------
// tile 128x128x64, 256 thr (8 warps 4x2, warp tile 32x64), 2-stage cp.async pipe
#define GS_A      16384u                    // 128 rows * 128 B
#define GS_STAGE  32768u                    // A + B per stage
#define GSM_DYN   (2 * GS_STAGE + 128)

__global__ void __launch_bounds__(256) gemm_mma_kernel(const int* __restrict__ memptr_p) {
    int rowsEff = B_ROWS + memptr_p[0];
    int rowBase = blockIdx.y * 128;
    if (rowBase >= rowsEff) return;
    int colBase = blockIdx.x * 128;

    extern __shared__ char dynsm[];
    uint32_t sbase = (smem_to_u32(dynsm) + 127u) & ~127u;

    int tid = threadIdx.x;
    int warp = tid >> 5, lane = tid & 31;
    int lrow = tid >> 1, lhalf = tid & 1;   // loader mapping: half-row (64B) per thread

    const char* aG = (const char*)(g_A16 + (size_t)(rowBase + lrow) * D_DIM) + lhalf * 64;
    const char* bG = (const char*)(g_B16 + (size_t)(colBase + lrow) * D_DIM) + lhalf * 64;
    uint32_t so[4];
    #pragma unroll
    for (int j = 0; j < 4; j++) {
        uint32_t off = (uint32_t)lrow * 128u + (uint32_t)lhalf * 64u + j * 16u;
        so[j] = off ^ ((off >> 3) & 0x70u);   // SW128 swizzle
    }

#define G_ISSUE(kt, s) do { \
        uint32_t as_ = sbase + (uint32_t)(s) * GS_STAGE; \
        uint32_t bs_ = as_ + GS_A; \
        const char* ag_ = aG + (size_t)(kt) * 128; \
        const char* bg_ = bG + (size_t)(kt) * 128; \
        _Pragma("unroll") \
        for (int j_ = 0; j_ < 4; j_++) { \
            cp16(as_ + so[j_], ag_ + j_ * 16); \
            cp16(bs_ + so[j_], bg_ + j_ * 16); \
        } \
    } while (0)

    float acc[2][8][4];
    #pragma unroll
    for (int mt = 0; mt < 2; mt++)
        #pragma unroll
        for (int nt = 0; nt < 8; nt++)
            #pragma unroll
            for (int q = 0; q < 4; q++) acc[mt][nt][q] = 0.0f;

    const int NT = D_DIM / 64;   // 16 k-tiles
    G_ISSUE(0, 0); CP_COMMIT();
    G_ISSUE(1, 1); CP_COMMIT();

    int m0 = (warp & 3) * 32, n0 = (warp >> 2) * 64;
    int flr = lane & 15;            // ldmatrix fragment row
    int fkh = (lane >> 4) * 16;     // ldmatrix k-half byte offset

    for (int kt = 0; kt < NT; kt++) {
        int s = kt & 1;
        uint32_t as_ = sbase + (uint32_t)s * GS_STAGE;
        uint32_t bs_ = as_ + GS_A;
        CP_WAIT1();
        __syncthreads();

        #pragma unroll
        for (int ks = 0; ks < 4; ks++) {
            uint32_t kb = (uint32_t)(ks * 32 + fkh);
            uint32_t afr[2][4];
            #pragma unroll
            for (int mt = 0; mt < 2; mt++) {
                uint32_t off = (uint32_t)(m0 + mt * 16 + flr) * 128u + kb;
                LDSM4(afr[mt], as_ + (off ^ ((off >> 3) & 0x70u)));
            }
            uint32_t bfr[4][4];
            #pragma unroll
            for (int p = 0; p < 4; p++) {
                uint32_t off = (uint32_t)(n0 + p * 16 + flr) * 128u + kb;
                LDSM4(bfr[p], bs_ + (off ^ ((off >> 3) & 0x70u)));
            }
            #pragma unroll
            for (int mt = 0; mt < 2; mt++)
                #pragma unroll
                for (int nt = 0; nt < 8; nt++) {
                    int p = nt >> 1, w = nt & 1;
                    MMA16816(acc[mt][nt], afr[mt], bfr[p][w], bfr[p][w + 2]);
                }
        }
        __syncthreads();
        if (kt + 2 < NT) G_ISSUE(kt + 2, s);
        CP_COMMIT();
    }

    // store C with *10 scaling; C-frag: c0,c1 -> (row lane/4, col 2*(lane%4)); c2,c3 -> row+8
    int mrow = lane >> 2;
    int ncol = (lane & 3) * 2;
    #pragma unroll
    for (int mt = 0; mt < 2; mt++)
        #pragma unroll
        for (int h = 0; h < 2; h++) {
            int r = rowBase + m0 + mt * 16 + h * 8 + mrow;
            if (r < rowsEff) {
                float* dst = g_sim + (size_t)r * C_CLS;
                #pragma unroll
                for (int nt = 0; nt < 8; nt++) {
                    int c = colBase + n0 + nt * 8 + ncol;
                    float v0 = acc[mt][nt][h * 2 + 0] * TEMP_INV;
                    float v1 = acc[mt][nt][h * 2 + 1] * TEMP_INV;
                    if (c + 1 < C_CLS) {
                        *(float2*)(dst + c) = make_float2(v0, v1);
                    } else if (c < C_CLS) {
                        dst[c] = v0;
                    }
                }
            }
        }
#undef G_ISSUE
}

// ---------------- epilogue: radix-select exact top-10 threshold + masked LSE ----------------
__global__ void __launch_bounds__(256) epilogue_kernel(const int* __restrict__ labels,
                                                       const int* __restrict__ memL,
                                                       const int* __restrict__ memptr_p) {
    int r = blockIdx.x;
    int mp = memptr_p[0];
    int rowsEff = B_ROWS + mp;
    if (r >= rowsEff) return;

    const int* lab = (r < B_ROWS) ? (labels + (size_t)r * C_CLS)
                                  : (memL + (size_t)(r - B_ROWS) * C_CLS);
    float wfac = (r < B_ROWS) ? 2.0f : 1.0f;   // z_img rows duplicated in enhanced set

    __shared__ float    s_val[C_CLS];
    __shared__ unsigned s_key[C_CLS];          // orderable key for negatives, 0 for positives
    __shared__ unsigned s_hist[4096];
    __shared__ unsigned s_gsum[256];
    __shared__ unsigned s_cand[1024];
    __shared__ unsigned s_cnt, s_bin, s_kp, s_thr;
    __shared__ float sredf[32];

    int tid = threadIdx.x;
    for (int i = tid; i < 4096; i += 256) s_hist[i] = 0u;
    if (tid == 0) { s_cnt = 0u; s_bin = 0u; s_thr = 0u; s_kp = 1u; }

    const float* simRow = g_sim + (size_t)r * C_CLS;
    for (int c = tid; c < C_CLS; c += 256) {
        float v = simRow[c];
        unsigned u = __float_as_uint(v);
        unsigned k = (u & 0x80000000u) ? ~u : (u | 0x80000000u);   // monotone key, > 0 finite
        s_val[c] = v;
        s_key[c] = (lab[c] > 0) ? 0u : k;
    }
    __syncthreads();

    for (int c = tid; c < C_CLS; c += 256) {
        unsigned k = s_key[c];
        if (k) atomicAdd(&s_hist[k >> 20], 1u);
    }
    __syncthreads();

    {   // group sums: 256 groups of 16 bins
        unsigned s = 0;
        #pragma unroll
        for (int j = 0; j < 16; j++) s += s_hist[tid * 16 + j];
        s_gsum[tid] = s;
    }
    __syncthreads();

    if (tid < 32) {   // locate bin of the 10th-largest negative (descending)
        int lane = tid;
        int gtop = 255 - 8 * lane;
        unsigned cj = 0;
        #pragma unroll
        for (int t = 0; t < 8; t++) cj += s_gsum[gtop - t];
        unsigned pre = cj;
        #pragma unroll
        for (int o = 1; o < 32; o <<= 1) {
            unsigned v = __shfl_up_sync(0xffffffffu, pre, o);
            if (lane >= o) pre += v;
        }
        unsigned total = __shfl_sync(0xffffffffu, pre, 31);
        unsigned excl = pre - cj;
        if (total < HARD_K) {
            if (lane == 0) { s_thr = 0u; s_bin = 0xffffffffu; }   // all negatives pass
        } else if (excl < HARD_K && pre >= HARD_K) {
            unsigned before = excl;
            int g = gtop;
            while (before + s_gsum[g] < HARD_K) { before += s_gsum[g]; g--; }
            int b = g * 16 + 15;
            while (before + s_hist[b] < HARD_K) { before += s_hist[b]; b--; }
            s_bin = (unsigned)b;
            s_kp = HARD_K - before;
        }
    }
    __syncthreads();

    unsigned binSel = s_bin;
    if (binSel != 0xffffffffu) {
        for (int c = tid; c < C_CLS; c += 256) {
            unsigned k = s_key[c];
            if (k && (k >> 20) == binSel) {
                unsigned idx = atomicAdd(&s_cnt, 1u);
                s_cand[idx] = k;
            }
        }
        __syncthreads();
        if (tid < 32) {   // k'-th largest among candidates (with multiplicity)
            int lane = tid;
            int cnt = (int)s_cnt;
            int kp = (int)s_kp;
            for (int it = 0; it < kp; it++) {
                unsigned mx = 0;
                for (int i = lane; i < cnt; i += 32) mx = max(mx, s_cand[i]);
                #pragma unroll
                for (int o = 16; o; o >>= 1) mx = max(mx, __shfl_xor_sync(0xffffffffu, mx, o));
                if (it == kp - 1) {
                    if (lane == 0) s_thr = mx;
                } else {
                    int mi = 0x7fffffff;
                    for (int i = lane; i < cnt; i += 32)
                        if (s_cand[i] == mx) mi = min(mi, i);
                    #pragma unroll
                    for (int o = 16; o; o >>= 1) mi = min(mi, __shfl_xor_sync(0xffffffffu, mi, o));
                    if (lane == 0) s_cand[mi] = 0u;
                    __syncwarp();
                }
            }
        }
    }
    __syncthreads();
    unsigned thr = s_thr;

    float lm = NEG_INF;
    for (int c = tid; c < C_CLS; c += 256) {
        unsigned k = s_key[c];
        if (k == 0u || k >= thr) lm = fmaxf(lm, s_val[c]);
    }
    float mx = blockReduceMaxF(lm, sredf);

    float se = 0.0f, ws = 0.0f, wv = 0.0f;
    for (int c = tid; c < C_CLS; c += 256) {
        unsigned k = s_key[c];
        float v = s_val[c];
        bool pos = (k == 0u);
        if (pos || k >= thr) se += expf(v - mx);
        if (pos) { float w = g_w[c]; ws += w; wv += w * v; }
    }
    se = blockReduceSumF(se, sredf);
    ws = blockReduceSumF(ws, sredf);
    wv = blockReduceSumF(wv, sredf);

    if (tid == 0 && ws > 0.0f) {
        float lse = mx + logf(se);
        atomicAdd(&g_loss, (double)(wfac * ((lse * ws - wv) / (ws + EPSF))));
        atomicAdd(&g_nvalid, (double)wfac);
    }
}

__global__ void finalize_kernel(float* __restrict__ out) {
    double nv = g_nvalid;
    if (nv < 1.0) nv = 1.0;
    out[0] = (float)(g_loss / nv);
}

// ---------------- launch ----------------
extern "C" void kernel_launch(void* const* d_in, const int* in_sizes, int n_in,
                              void* d_out, int out_size) {
    const float* img     = (const float*)d_in[0];
    const float* prompts = (const float*)d_in[1];
    const int*   labels  = (const int*)d_in[2];
    const float* memF    = (const float*)d_in[3];
    const int*   memL    = (const int*)d_in[4];
    const int*   memptr  = (const int*)d_in[5];
    float* out = (float*)d_out;
    (void)in_sizes; (void)n_in; (void)out_size;

    cudaFuncSetAttribute(gemm_mma_kernel, cudaFuncAttributeMaxDynamicSharedMemorySize, GSM_DYN);

    init_kernel<<<1, 1024>>>();
    norm_prompts_kernel<<<1024, 256>>>(prompts);
    norm_img_kernel<<<B_ROWS, 256>>>(img);
    conv_mem_kernel<<<M_ROWS, 256>>>(memF, memptr);
    counts_kernel<<<dim3(4, 32), 256>>>(labels);
    weights_kernel<<<1, 1024>>>();
    gemm_mma_kernel<<<dim3(8, MAXR / 128), 256, GSM_DYN>>>(memptr);
    epilogue_kernel<<<MAXR, 256>>>(labels, memL, memptr);
    finalize_kernel<<<1, 1>>>(out);
}